// round 1
// baseline (speedup 1.0000x reference)
#include <cuda_runtime.h>
#include <cuda_bf16.h>
#include <math.h>

// ---------------------------------------------------------------------------
// Problem constants (shapes fixed by the reference)
// ---------------------------------------------------------------------------
#define N_NODES   100000
#define FAN_IN    512
#define FAN_MID   256
#define FAN_OUT   64

// ---------------------------------------------------------------------------
// Scratch (device globals; allocation is forbidden)
// ---------------------------------------------------------------------------
__device__ float g_sup1[(size_t)N_NODES * FAN_MID];   // x @ W1            (100k x 256)
__device__ float g_agg1[(size_t)N_NODES * FAN_MID];   // A @ sup1 (+b1, lrelu in place)
__device__ float g_sup2[(size_t)N_NODES * FAN_OUT];   // h @ W2            (100k x 64)
__device__ float g_agg2[(size_t)N_NODES * FAN_OUT];   // A @ sup2

// ---------------------------------------------------------------------------
// Zero-fill
// ---------------------------------------------------------------------------
__global__ void zero_kernel(float* __restrict__ p, int n) {
    int i = blockIdx.x * blockDim.x + threadIdx.x;
    int stride = gridDim.x * blockDim.x;
    for (; i < n; i += stride) p[i] = 0.0f;
}

// ---------------------------------------------------------------------------
// Tiled fp32 GEMM: C[M,N] = A[M,K] @ B[K,N]
// BM=64, BN=64, BK=16, 256 threads, 4x4 per thread.
// ---------------------------------------------------------------------------
__global__ void gemm64(const float* __restrict__ A, const float* __restrict__ B,
                       float* __restrict__ C, int M, int N, int K) {
    __shared__ float As[16][64];
    __shared__ float Bs[16][68];

    const int tid = threadIdx.x;
    const int bm = blockIdx.y * 64;
    const int bn = blockIdx.x * 64;
    const int ty = tid >> 4;      // 0..15
    const int tx = tid & 15;      // 0..15

    float acc[4][4] = {};

    for (int k0 = 0; k0 < K; k0 += 16) {
        // Load A tile: 64 rows x 16 k (coalesced 16-wide per row)
        {
            int k = tid & 15;
            int m = tid >> 4;  // 0..15
            #pragma unroll
            for (int i = 0; i < 4; i++) {
                int row = bm + m + i * 16;
                As[k][m + i * 16] = (row < M) ? A[(size_t)row * K + k0 + k] : 0.0f;
            }
        }
        // Load B tile: 16 k x 64 n (coalesced 64-wide per row)
        {
            int n = tid & 63;
            int k = tid >> 6;  // 0..3
            #pragma unroll
            for (int i = 0; i < 4; i++) {
                Bs[k + i * 4][n] = B[(size_t)(k0 + k + i * 4) * N + bn + n];
            }
        }
        __syncthreads();

        #pragma unroll
        for (int kk = 0; kk < 16; kk++) {
            float a[4], b[4];
            #pragma unroll
            for (int i = 0; i < 4; i++) a[i] = As[kk][ty * 4 + i];
            #pragma unroll
            for (int j = 0; j < 4; j++) b[j] = Bs[kk][tx * 4 + j];
            #pragma unroll
            for (int i = 0; i < 4; i++)
                #pragma unroll
                for (int j = 0; j < 4; j++)
                    acc[i][j] += a[i] * b[j];
        }
        __syncthreads();
    }

    #pragma unroll
    for (int i = 0; i < 4; i++) {
        int row = bm + ty * 4 + i;
        if (row < M) {
            #pragma unroll
            for (int j = 0; j < 4; j++)
                C[(size_t)row * N + bn + tx * 4 + j] = acc[i][j];
        }
    }
}

// ---------------------------------------------------------------------------
// Edge gather/scale/scatter-add: agg[dst] += sup[src] * w, F features/row.
// 256-thread blocks, (256/F) edges per block.
// ---------------------------------------------------------------------------
template <int F>
__global__ void scatter_kernel(const int* __restrict__ src, const int* __restrict__ dst,
                               const float* __restrict__ w,
                               const float* __restrict__ sup, float* __restrict__ agg,
                               int E) {
    const int EPB = 256 / F;
    int e = blockIdx.x * EPB + threadIdx.x / F;
    if (e >= E) return;
    int f = threadIdx.x % F;
    int s = src[e];
    int d = dst[e];
    float we = w[e];
    atomicAdd(&agg[(size_t)d * F + f], sup[(size_t)s * F + f] * we);
}

// ---------------------------------------------------------------------------
// h = leaky_relu(agg + b), in place. rows x 256
// ---------------------------------------------------------------------------
__global__ void bias_lrelu_kernel(float* __restrict__ a, const float* __restrict__ b,
                                  int total) {
    int i = blockIdx.x * blockDim.x + threadIdx.x;
    if (i >= total) return;
    float v = a[i] + b[i & (FAN_MID - 1)];
    a[i] = (v > 0.0f) ? v : 0.01f * v;
}

// ---------------------------------------------------------------------------
// out = log_softmax(agg + b2) over 64 cols. One warp per row.
// ---------------------------------------------------------------------------
__global__ void lsm_kernel(const float* __restrict__ agg, const float* __restrict__ b,
                           float* __restrict__ out, int rows) {
    int warp = (blockIdx.x * blockDim.x + threadIdx.x) >> 5;
    int lane = threadIdx.x & 31;
    if (warp >= rows) return;
    const float* r = agg + (size_t)warp * FAN_OUT;
    float v0 = r[lane] + b[lane];
    float v1 = r[lane + 32] + b[lane + 32];
    float m = fmaxf(v0, v1);
    #pragma unroll
    for (int o = 16; o; o >>= 1) m = fmaxf(m, __shfl_xor_sync(0xFFFFFFFFu, m, o));
    float s = expf(v0 - m) + expf(v1 - m);
    #pragma unroll
    for (int o = 16; o; o >>= 1) s += __shfl_xor_sync(0xFFFFFFFFu, s, o);
    float lse = m + logf(s);
    out[(size_t)warp * FAN_OUT + lane] = v0 - lse;
    out[(size_t)warp * FAN_OUT + lane + 32] = v1 - lse;
}

// ---------------------------------------------------------------------------
// Launch
// ---------------------------------------------------------------------------
extern "C" void kernel_launch(void* const* d_in, const int* in_sizes, int n_in,
                              void* d_out, int out_size) {
    const float* x        = (const float*)d_in[0];
    const int*   edge_src = (const int*)  d_in[1];
    const int*   edge_dst = (const int*)  d_in[2];
    const float* edge_w1  = (const float*)d_in[3];
    const float* edge_w2  = (const float*)d_in[4];
    const float* W1       = (const float*)d_in[5];
    const float* b1       = (const float*)d_in[6];
    const float* W2       = (const float*)d_in[7];
    const float* b2       = (const float*)d_in[8];
    float* out = (float*)d_out;

    const int E = in_sizes[1];
    const int N = in_sizes[0] / FAN_IN;   // 100000

    float *sup1, *agg1, *sup2, *agg2;
    cudaGetSymbolAddress((void**)&sup1, g_sup1);
    cudaGetSymbolAddress((void**)&agg1, g_agg1);
    cudaGetSymbolAddress((void**)&sup2, g_sup2);
    cudaGetSymbolAddress((void**)&agg2, g_agg2);

    const int mid_total = N * FAN_MID;   // 25.6M
    const int out_total = N * FAN_OUT;   // 6.4M

    // Zero aggregation buffers
    zero_kernel<<<2048, 256>>>(agg1, mid_total);
    zero_kernel<<<2048, 256>>>(agg2, out_total);

    // Layer 1: support = x @ W1
    {
        dim3 grid(FAN_MID / 64, (N + 63) / 64);
        gemm64<<<grid, 256>>>(x, W1, sup1, N, FAN_MID, FAN_IN);
    }
    // Edge pass 1: agg1[dst] += sup1[src] * w1
    scatter_kernel<FAN_MID><<<E, 256>>>(edge_src, edge_dst, edge_w1, sup1, agg1, E);

    // h = leaky_relu(agg1 + b1) in place
    bias_lrelu_kernel<<<(mid_total + 255) / 256, 256>>>(agg1, b1, mid_total);

    // Layer 2: support2 = h @ W2
    {
        dim3 grid(FAN_OUT / 64, (N + 63) / 64);
        gemm64<<<grid, 256>>>(agg1, W2, sup2, N, FAN_OUT, FAN_MID);
    }
    // Edge pass 2: agg2[dst] += sup2[src] * w2
    scatter_kernel<FAN_OUT><<<(E + 3) / 4, 256>>>(edge_src, edge_dst, edge_w2, sup2, agg2, E);

    // log_softmax(agg2 + b2)
    lsm_kernel<<<(N * 32 + 255) / 256, 256>>>(agg2, b2, out, N);
}

// round 2
// speedup vs baseline: 3.8759x; 3.8759x over previous
#include <cuda_runtime.h>
#include <cuda_bf16.h>
#include <math.h>

#define N_NODES   100000
#define N_EDGES   3200000
#define FAN_IN    512
#define FAN_MID   256
#define FAN_OUT   64

// ---------------------------------------------------------------------------
// Scratch (device globals; allocation forbidden)
// ---------------------------------------------------------------------------
__device__ float g_sup1[(size_t)N_NODES * FAN_MID];   // x @ W1
__device__ float g_h   [(size_t)N_NODES * FAN_MID];   // lrelu(A@sup1 + b1)
__device__ float g_sup2[(size_t)N_NODES * FAN_OUT];   // h @ W2

__device__ int   g_cnt    [N_NODES];
__device__ int   g_row_ptr[N_NODES + 1];
__device__ int   g_fill   [N_NODES];
__device__ int   g_csr_src[N_EDGES];
__device__ float g_csr_w1 [N_EDGES];
__device__ float g_csr_w2 [N_EDGES];

// ---------------------------------------------------------------------------
// CSR build: histogram -> scan -> fill (reordering src/w1/w2 by dst)
// ---------------------------------------------------------------------------
__global__ void zero_int_kernel(int* __restrict__ p, int n) {
    int i = blockIdx.x * blockDim.x + threadIdx.x;
    int st = gridDim.x * blockDim.x;
    for (; i < n; i += st) p[i] = 0;
}

__global__ void hist_kernel(const int* __restrict__ dst, int* __restrict__ cnt, int E) {
    int i = blockIdx.x * blockDim.x + threadIdx.x;
    int st = gridDim.x * blockDim.x;
    for (; i < E; i += st) atomicAdd(&cnt[dst[i]], 1);
}

// Single-block chunked exclusive scan (n ~ 100k -> ~98 chunk iterations)
__global__ void scan_kernel(const int* __restrict__ cnt, int* __restrict__ row_ptr, int n) {
    __shared__ int wsum[32];
    const int tid = threadIdx.x;
    const int lane = tid & 31;
    const int wid = tid >> 5;                 // 0..31 (1024 threads)
    int carry = 0;
    for (int base = 0; base < n; base += 1024) {
        int i = base + tid;
        int v = (i < n) ? cnt[i] : 0;
        int x = v;
        #pragma unroll
        for (int o = 1; o < 32; o <<= 1) {
            int y = __shfl_up_sync(0xFFFFFFFFu, x, o);
            if (lane >= o) x += y;
        }
        if (lane == 31) wsum[wid] = x;
        __syncthreads();
        if (wid == 0) {
            int s = wsum[lane];
            #pragma unroll
            for (int o = 1; o < 32; o <<= 1) {
                int y = __shfl_up_sync(0xFFFFFFFFu, s, o);
                if (lane >= o) s += y;
            }
            wsum[lane] = s;
        }
        __syncthreads();
        int warp_off = (wid > 0) ? wsum[wid - 1] : 0;
        if (i < n) row_ptr[i] = carry + warp_off + (x - v);
        int total = wsum[31];
        __syncthreads();
        carry += total;
    }
    if (tid == 0) row_ptr[n] = carry;
}

__global__ void copy_int_kernel(const int* __restrict__ a, int* __restrict__ b, int n) {
    int i = blockIdx.x * blockDim.x + threadIdx.x;
    int st = gridDim.x * blockDim.x;
    for (; i < n; i += st) b[i] = a[i];
}

__global__ void fill_kernel(const int* __restrict__ src, const int* __restrict__ dst,
                            const float* __restrict__ w1, const float* __restrict__ w2,
                            int* __restrict__ fill,
                            int* __restrict__ csr_src, float* __restrict__ csr_w1,
                            float* __restrict__ csr_w2, int E) {
    int i = blockIdx.x * blockDim.x + threadIdx.x;
    int st = gridDim.x * blockDim.x;
    for (; i < E; i += st) {
        int d = dst[i];
        int pos = atomicAdd(&fill[d], 1);
        csr_src[pos] = src[i];
        csr_w1[pos]  = w1[i];
        csr_w2[pos]  = w2[i];
    }
}

// ---------------------------------------------------------------------------
// Tiled fp32 GEMM: C[M,N] = A[M,K] @ B[K,N]
// BM=128, BK=16, 256 threads. BN/TN templated (128/8 for GEMM1, 64/4 for GEMM2)
// ---------------------------------------------------------------------------
template <int BN, int TN>
__global__ void gemm_kernel(const float* __restrict__ A, const float* __restrict__ B,
                            float* __restrict__ C, int M, int N, int K) {
    __shared__ float As[16][132];
    __shared__ float Bs[16][BN + 4];

    const int tid = threadIdx.x;
    const int bm = blockIdx.y * 128;
    const int bn = blockIdx.x * BN;
    const int tx = tid & 15;   // 0..15
    const int ty = tid >> 4;   // 0..15

    float acc[8][TN];
    #pragma unroll
    for (int i = 0; i < 8; i++)
        #pragma unroll
        for (int j = 0; j < TN; j++) acc[i][j] = 0.0f;

    for (int k0 = 0; k0 < K; k0 += 16) {
        // A tile: 128 rows x 16 k = 512 float4s, 2 per thread (transposed into As)
        #pragma unroll
        for (int i = 0; i < 2; i++) {
            int f4 = tid + i * 256;
            int m = f4 >> 2;
            int kq = (f4 & 3) * 4;
            int row = bm + m;
            float4 v = make_float4(0.f, 0.f, 0.f, 0.f);
            if (row < M) v = *(const float4*)&A[(size_t)row * K + k0 + kq];
            As[kq + 0][m] = v.x;
            As[kq + 1][m] = v.y;
            As[kq + 2][m] = v.z;
            As[kq + 3][m] = v.w;
        }
        // B tile: 16 k x BN
        constexpr int BF4 = (16 * BN / 4) / 256;  // 2 (BN=128) or 1 (BN=64)
        #pragma unroll
        for (int i = 0; i < BF4; i++) {
            int f4 = tid + i * 256;
            int k = f4 / (BN / 4);
            int n4 = (f4 % (BN / 4)) * 4;
            float4 v = *(const float4*)&B[(size_t)(k0 + k) * N + bn + n4];
            Bs[k][n4 + 0] = v.x;
            Bs[k][n4 + 1] = v.y;
            Bs[k][n4 + 2] = v.z;
            Bs[k][n4 + 3] = v.w;
        }
        __syncthreads();

        #pragma unroll
        for (int kk = 0; kk < 16; kk++) {
            float a[8], b[TN];
            #pragma unroll
            for (int i = 0; i < 8; i++) a[i] = As[kk][ty * 8 + i];
            #pragma unroll
            for (int j = 0; j < TN; j++) b[j] = Bs[kk][tx * TN + j];
            #pragma unroll
            for (int i = 0; i < 8; i++)
                #pragma unroll
                for (int j = 0; j < TN; j++) acc[i][j] += a[i] * b[j];
        }
        __syncthreads();
    }

    #pragma unroll
    for (int i = 0; i < 8; i++) {
        int row = bm + ty * 8 + i;
        if (row < M) {
            #pragma unroll
            for (int j = 0; j < TN; j += 4) {
                float4 v = make_float4(acc[i][j], acc[i][j + 1], acc[i][j + 2], acc[i][j + 3]);
                *(float4*)&C[(size_t)row * N + bn + tx * TN + j] = v;
            }
        }
    }
}

// ---------------------------------------------------------------------------
// Gather layer 1 (F=256): h[node] = lrelu(sum_e w*sup1[src] + b1)
// 64 threads per node (float4 per thread), 4 nodes per 256-thread block.
// ---------------------------------------------------------------------------
__global__ void gather1_kernel(const int* __restrict__ row_ptr, const int* __restrict__ csr_src,
                               const float* __restrict__ csr_w,
                               const float* __restrict__ sup, const float* __restrict__ b,
                               float* __restrict__ h, int n) {
    int node = blockIdx.x * 4 + (threadIdx.x >> 6);
    if (node >= n) return;
    int lane64 = threadIdx.x & 63;
    int p0 = row_ptr[node], p1 = row_ptr[node + 1];
    float4 acc = make_float4(0.f, 0.f, 0.f, 0.f);
    for (int p = p0; p < p1; p++) {
        int s = __ldg(&csr_src[p]);
        float w = __ldg(&csr_w[p]);
        float4 v = *(const float4*)&sup[(size_t)s * FAN_MID + lane64 * 4];
        acc.x += w * v.x;
        acc.y += w * v.y;
        acc.z += w * v.z;
        acc.w += w * v.w;
    }
    float4 bb = *(const float4*)&b[lane64 * 4];
    acc.x += bb.x; acc.y += bb.y; acc.z += bb.z; acc.w += bb.w;
    acc.x = (acc.x > 0.f) ? acc.x : 0.01f * acc.x;
    acc.y = (acc.y > 0.f) ? acc.y : 0.01f * acc.y;
    acc.z = (acc.z > 0.f) ? acc.z : 0.01f * acc.z;
    acc.w = (acc.w > 0.f) ? acc.w : 0.01f * acc.w;
    *(float4*)&h[(size_t)node * FAN_MID + lane64 * 4] = acc;
}

// ---------------------------------------------------------------------------
// Gather layer 2 (F=64) fused with bias + log_softmax.
// 1 warp per node (2 features per lane), 8 nodes per 256-thread block.
// ---------------------------------------------------------------------------
__global__ void gather2_lsm_kernel(const int* __restrict__ row_ptr, const int* __restrict__ csr_src,
                                   const float* __restrict__ csr_w,
                                   const float* __restrict__ sup, const float* __restrict__ b,
                                   float* __restrict__ out, int n) {
    int node = blockIdx.x * 8 + (threadIdx.x >> 5);
    if (node >= n) return;
    int lane = threadIdx.x & 31;
    int p0 = row_ptr[node], p1 = row_ptr[node + 1];
    float a0 = 0.f, a1 = 0.f;
    for (int p = p0; p < p1; p++) {
        int s = __ldg(&csr_src[p]);
        float w = __ldg(&csr_w[p]);
        a0 += w * sup[(size_t)s * FAN_OUT + lane];
        a1 += w * sup[(size_t)s * FAN_OUT + lane + 32];
    }
    a0 += b[lane];
    a1 += b[lane + 32];
    float m = fmaxf(a0, a1);
    #pragma unroll
    for (int o = 16; o; o >>= 1) m = fmaxf(m, __shfl_xor_sync(0xFFFFFFFFu, m, o));
    float s2 = expf(a0 - m) + expf(a1 - m);
    #pragma unroll
    for (int o = 16; o; o >>= 1) s2 += __shfl_xor_sync(0xFFFFFFFFu, s2, o);
    float lse = m + logf(s2);
    out[(size_t)node * FAN_OUT + lane]      = a0 - lse;
    out[(size_t)node * FAN_OUT + lane + 32] = a1 - lse;
}

// ---------------------------------------------------------------------------
// Launch
// ---------------------------------------------------------------------------
extern "C" void kernel_launch(void* const* d_in, const int* in_sizes, int n_in,
                              void* d_out, int out_size) {
    const float* x        = (const float*)d_in[0];
    const int*   edge_src = (const int*)  d_in[1];
    const int*   edge_dst = (const int*)  d_in[2];
    const float* edge_w1  = (const float*)d_in[3];
    const float* edge_w2  = (const float*)d_in[4];
    const float* W1       = (const float*)d_in[5];
    const float* b1       = (const float*)d_in[6];
    const float* W2       = (const float*)d_in[7];
    const float* b2       = (const float*)d_in[8];
    float* out = (float*)d_out;

    const int E = in_sizes[1];
    const int N = in_sizes[0] / FAN_IN;

    float *sup1, *h, *sup2, *csr_w1, *csr_w2;
    int *cnt, *row_ptr, *fill, *csr_src;
    cudaGetSymbolAddress((void**)&sup1, g_sup1);
    cudaGetSymbolAddress((void**)&h, g_h);
    cudaGetSymbolAddress((void**)&sup2, g_sup2);
    cudaGetSymbolAddress((void**)&cnt, g_cnt);
    cudaGetSymbolAddress((void**)&row_ptr, g_row_ptr);
    cudaGetSymbolAddress((void**)&fill, g_fill);
    cudaGetSymbolAddress((void**)&csr_src, g_csr_src);
    cudaGetSymbolAddress((void**)&csr_w1, g_csr_w1);
    cudaGetSymbolAddress((void**)&csr_w2, g_csr_w2);

    // --- CSR build (overlappable with GEMM1 in principle; serial is fine) ---
    zero_int_kernel<<<256, 256>>>(cnt, N);
    hist_kernel<<<2048, 256>>>(edge_dst, cnt, E);
    scan_kernel<<<1, 1024>>>(cnt, row_ptr, N);
    copy_int_kernel<<<256, 256>>>(row_ptr, fill, N);
    fill_kernel<<<2048, 256>>>(edge_src, edge_dst, edge_w1, edge_w2,
                               fill, csr_src, csr_w1, csr_w2, E);

    // --- Layer 1: sup1 = x @ W1 ---
    {
        dim3 grid(FAN_MID / 128, (N + 127) / 128);
        gemm_kernel<128, 8><<<grid, 256>>>(x, W1, sup1, N, FAN_MID, FAN_IN);
    }
    // h = lrelu(A @ sup1 + b1)
    gather1_kernel<<<(N + 3) / 4, 256>>>(row_ptr, csr_src, csr_w1, sup1, b1, h, N);

    // --- Layer 2: sup2 = h @ W2 ---
    {
        dim3 grid(FAN_OUT / 64, (N + 127) / 128);
        gemm_kernel<64, 4><<<grid, 256>>>(h, W2, sup2, N, FAN_OUT, FAN_MID);
    }
    // out = log_softmax(A @ sup2 + b2)
    gather2_lsm_kernel<<<(N + 7) / 8, 256>>>(row_ptr, csr_src, csr_w2, sup2, b2, out, N);
}

// round 3
// speedup vs baseline: 5.3447x; 1.3789x over previous
#include <cuda_runtime.h>
#include <cuda_bf16.h>
#include <math.h>

#define N_NODES   100000
#define N_EDGES   3200000
#define FAN_IN    512
#define FAN_MID   256
#define FAN_OUT   64

// ---------------------------------------------------------------------------
// Scratch (device globals; allocation forbidden)
// ---------------------------------------------------------------------------
__device__ float g_sup1[(size_t)N_NODES * FAN_MID];   // x @ W1
__device__ float g_h   [(size_t)N_NODES * FAN_MID];   // lrelu(A@sup1 + b1)
__device__ float g_sup2[(size_t)N_NODES * FAN_OUT];   // h @ W2

__device__ int   g_cnt    [N_NODES];
__device__ int   g_row_ptr[N_NODES + 1];
__device__ int   g_fill   [N_NODES];
__device__ int   g_csr_src[N_EDGES];
__device__ float g_csr_w1 [N_EDGES];
__device__ float g_csr_w2 [N_EDGES];

// ---------------------------------------------------------------------------
// CSR build: histogram -> scan -> fill (reordering src/w1/w2 by dst)
// ---------------------------------------------------------------------------
__global__ void zero_int_kernel(int* __restrict__ p, int n) {
    int i = blockIdx.x * blockDim.x + threadIdx.x;
    int st = gridDim.x * blockDim.x;
    for (; i < n; i += st) p[i] = 0;
}

__global__ void hist_kernel(const int* __restrict__ dst, int* __restrict__ cnt, int E) {
    int i = blockIdx.x * blockDim.x + threadIdx.x;
    int st = gridDim.x * blockDim.x;
    for (; i < E; i += st) atomicAdd(&cnt[dst[i]], 1);
}

// Single-block chunked exclusive scan; writes row_ptr AND fill (working copy).
__global__ void scan_kernel(const int* __restrict__ cnt, int* __restrict__ row_ptr,
                            int* __restrict__ fill, int n) {
    __shared__ int wsum[32];
    const int tid = threadIdx.x;
    const int lane = tid & 31;
    const int wid = tid >> 5;
    int carry = 0;
    for (int base = 0; base < n; base += 1024) {
        int i = base + tid;
        int v = (i < n) ? cnt[i] : 0;
        int x = v;
        #pragma unroll
        for (int o = 1; o < 32; o <<= 1) {
            int y = __shfl_up_sync(0xFFFFFFFFu, x, o);
            if (lane >= o) x += y;
        }
        if (lane == 31) wsum[wid] = x;
        __syncthreads();
        if (wid == 0) {
            int s = wsum[lane];
            #pragma unroll
            for (int o = 1; o < 32; o <<= 1) {
                int y = __shfl_up_sync(0xFFFFFFFFu, s, o);
                if (lane >= o) s += y;
            }
            wsum[lane] = s;
        }
        __syncthreads();
        int warp_off = (wid > 0) ? wsum[wid - 1] : 0;
        if (i < n) {
            int ex = carry + warp_off + (x - v);
            row_ptr[i] = ex;
            fill[i] = ex;
        }
        int total = wsum[31];
        __syncthreads();
        carry += total;
    }
    if (tid == 0) row_ptr[n] = carry;
}

__global__ void fill_kernel(const int* __restrict__ src, const int* __restrict__ dst,
                            const float* __restrict__ w1, const float* __restrict__ w2,
                            int* __restrict__ fill,
                            int* __restrict__ csr_src, float* __restrict__ csr_w1,
                            float* __restrict__ csr_w2, int E) {
    int i = blockIdx.x * blockDim.x + threadIdx.x;
    int st = gridDim.x * blockDim.x;
    for (; i < E; i += st) {
        int d = dst[i];
        int pos = atomicAdd(&fill[d], 1);
        csr_src[pos] = src[i];
        csr_w1[pos]  = w1[i];
        csr_w2[pos]  = w2[i];
    }
}

// ---------------------------------------------------------------------------
// tf32 helpers
// ---------------------------------------------------------------------------
__device__ __forceinline__ unsigned f2tf32(float f) {
    unsigned r;
    asm("cvt.rna.tf32.f32 %0, %1;" : "=r"(r) : "f"(f));
    return r;
}

__device__ __forceinline__ void mma_tf32(float& c0, float& c1, float& c2, float& c3,
                                         unsigned a0, unsigned a1, unsigned a2, unsigned a3,
                                         unsigned b0, unsigned b1) {
    asm volatile(
        "mma.sync.aligned.m16n8k8.row.col.f32.tf32.tf32.f32 "
        "{%0,%1,%2,%3}, {%4,%5,%6,%7}, {%8,%9}, {%0,%1,%2,%3};"
        : "+f"(c0), "+f"(c1), "+f"(c2), "+f"(c3)
        : "r"(a0), "r"(a1), "r"(a2), "r"(a3), "r"(b0), "r"(b1));
}

// ---------------------------------------------------------------------------
// tf32 tensor-core GEMM: C[M,N] = A[M,K] @ B[K,N]
// BM=128, BN=128, BK=32. 256 threads = 8 warps (4 m x 2 n), warptile 32x64.
// Per warp per k8: 2 m-tiles (m16) x 8 n-tiles (n8) = 16 mma.
// ---------------------------------------------------------------------------
__global__ __launch_bounds__(256) void gemm_tf32_kernel(
    const float* __restrict__ A, const float* __restrict__ B,
    float* __restrict__ C, int M, int N, int K) {
    __shared__ unsigned As[128][36];   // [m][k], pad 36: frag loads conflict-free
    __shared__ unsigned Bs[128][34];   // [n][k], pad 34

    const int tid = threadIdx.x;
    const int lane = tid & 31;
    const int wid = tid >> 5;
    const int warp_m = wid & 3;        // 0..3
    const int warp_n = wid >> 2;       // 0..1
    const int bm = blockIdx.y * 128;
    const int bn = blockIdx.x * 128;
    const int g = lane >> 2;           // groupID 0..7
    const int tg = lane & 3;           // thread-in-group 0..3

    float acc[2][8][4];
    #pragma unroll
    for (int i = 0; i < 2; i++)
        #pragma unroll
        for (int j = 0; j < 8; j++)
            #pragma unroll
            for (int c = 0; c < 4; c++) acc[i][j][c] = 0.0f;

    for (int k0 = 0; k0 < K; k0 += 32) {
        // --- A tile: 128 rows x 32 k = 1024 float4, 4 per thread ---
        #pragma unroll
        for (int i = 0; i < 4; i++) {
            int f4 = tid + i * 256;
            int row = f4 >> 3;           // 8 float4 per row
            int kq = (f4 & 7) * 4;
            float4 v = make_float4(0.f, 0.f, 0.f, 0.f);
            if (bm + row < M) v = *(const float4*)&A[(size_t)(bm + row) * K + k0 + kq];
            As[row][kq + 0] = f2tf32(v.x);
            As[row][kq + 1] = f2tf32(v.y);
            As[row][kq + 2] = f2tf32(v.z);
            As[row][kq + 3] = f2tf32(v.w);
        }
        // --- B tile: 32 k x 128 n, stored transposed Bs[n][k] ---
        #pragma unroll
        for (int i = 0; i < 4; i++) {
            int f4 = tid + i * 256;
            int k = f4 >> 5;             // 32 float4 per k row
            int n4 = (f4 & 31) * 4;
            float4 v = *(const float4*)&B[(size_t)(k0 + k) * N + bn + n4];
            Bs[n4 + 0][k] = f2tf32(v.x);
            Bs[n4 + 1][k] = f2tf32(v.y);
            Bs[n4 + 2][k] = f2tf32(v.z);
            Bs[n4 + 3][k] = f2tf32(v.w);
        }
        __syncthreads();

        #pragma unroll
        for (int kk = 0; kk < 32; kk += 8) {
            unsigned a[2][4];
            #pragma unroll
            for (int mt = 0; mt < 2; mt++) {
                int rb = warp_m * 32 + mt * 16 + g;
                a[mt][0] = As[rb][kk + tg];
                a[mt][1] = As[rb + 8][kk + tg];
                a[mt][2] = As[rb][kk + 4 + tg];
                a[mt][3] = As[rb + 8][kk + 4 + tg];
            }
            unsigned b[8][2];
            #pragma unroll
            for (int nt = 0; nt < 8; nt++) {
                int nb = warp_n * 64 + nt * 8 + g;
                b[nt][0] = Bs[nb][kk + tg];
                b[nt][1] = Bs[nb][kk + 4 + tg];
            }
            #pragma unroll
            for (int mt = 0; mt < 2; mt++)
                #pragma unroll
                for (int nt = 0; nt < 8; nt++)
                    mma_tf32(acc[mt][nt][0], acc[mt][nt][1], acc[mt][nt][2], acc[mt][nt][3],
                             a[mt][0], a[mt][1], a[mt][2], a[mt][3],
                             b[nt][0], b[nt][1]);
        }
        __syncthreads();
    }

    // --- Epilogue: c0,c1 at (row=g, col=2*tg), c2,c3 at (row=g+8) ---
    #pragma unroll
    for (int mt = 0; mt < 2; mt++) {
        #pragma unroll
        for (int nt = 0; nt < 8; nt++) {
            int col = bn + warp_n * 64 + nt * 8 + tg * 2;
            int r0 = bm + warp_m * 32 + mt * 16 + g;
            if (r0 < M)
                *(float2*)&C[(size_t)r0 * N + col] = make_float2(acc[mt][nt][0], acc[mt][nt][1]);
            int r1 = r0 + 8;
            if (r1 < M)
                *(float2*)&C[(size_t)r1 * N + col] = make_float2(acc[mt][nt][2], acc[mt][nt][3]);
        }
    }
}

// ---------------------------------------------------------------------------
// fp32 tiled GEMM (layer 2): BM=128, BN=64, BK=16, 256 threads, 8x4/thread
// ---------------------------------------------------------------------------
template <int BN, int TN>
__global__ void gemm_kernel(const float* __restrict__ A, const float* __restrict__ B,
                            float* __restrict__ C, int M, int N, int K) {
    __shared__ float As[16][132];
    __shared__ float Bs[16][BN + 4];

    const int tid = threadIdx.x;
    const int bm = blockIdx.y * 128;
    const int bn = blockIdx.x * BN;
    const int tx = tid & 15;
    const int ty = tid >> 4;

    float acc[8][TN];
    #pragma unroll
    for (int i = 0; i < 8; i++)
        #pragma unroll
        for (int j = 0; j < TN; j++) acc[i][j] = 0.0f;

    for (int k0 = 0; k0 < K; k0 += 16) {
        #pragma unroll
        for (int i = 0; i < 2; i++) {
            int f4 = tid + i * 256;
            int m = f4 >> 2;
            int kq = (f4 & 3) * 4;
            int row = bm + m;
            float4 v = make_float4(0.f, 0.f, 0.f, 0.f);
            if (row < M) v = *(const float4*)&A[(size_t)row * K + k0 + kq];
            As[kq + 0][m] = v.x;
            As[kq + 1][m] = v.y;
            As[kq + 2][m] = v.z;
            As[kq + 3][m] = v.w;
        }
        constexpr int BF4 = (16 * BN / 4) / 256;
        #pragma unroll
        for (int i = 0; i < BF4; i++) {
            int f4 = tid + i * 256;
            int k = f4 / (BN / 4);
            int n4 = (f4 % (BN / 4)) * 4;
            float4 v = *(const float4*)&B[(size_t)(k0 + k) * N + bn + n4];
            Bs[k][n4 + 0] = v.x;
            Bs[k][n4 + 1] = v.y;
            Bs[k][n4 + 2] = v.z;
            Bs[k][n4 + 3] = v.w;
        }
        __syncthreads();

        #pragma unroll
        for (int kk = 0; kk < 16; kk++) {
            float a[8], b[TN];
            #pragma unroll
            for (int i = 0; i < 8; i++) a[i] = As[kk][ty * 8 + i];
            #pragma unroll
            for (int j = 0; j < TN; j++) b[j] = Bs[kk][tx * TN + j];
            #pragma unroll
            for (int i = 0; i < 8; i++)
                #pragma unroll
                for (int j = 0; j < TN; j++) acc[i][j] += a[i] * b[j];
        }
        __syncthreads();
    }

    #pragma unroll
    for (int i = 0; i < 8; i++) {
        int row = bm + ty * 8 + i;
        if (row < M) {
            #pragma unroll
            for (int j = 0; j < TN; j += 4) {
                float4 v = make_float4(acc[i][j], acc[i][j + 1], acc[i][j + 2], acc[i][j + 3]);
                *(float4*)&C[(size_t)row * N + bn + tx * TN + j] = v;
            }
        }
    }
}

// ---------------------------------------------------------------------------
// Gather layer 1 (F=256): h[node] = lrelu(sum_e w*sup1[src] + b1)
// ---------------------------------------------------------------------------
__global__ void gather1_kernel(const int* __restrict__ row_ptr, const int* __restrict__ csr_src,
                               const float* __restrict__ csr_w,
                               const float* __restrict__ sup, const float* __restrict__ b,
                               float* __restrict__ h, int n) {
    int node = blockIdx.x * 4 + (threadIdx.x >> 6);
    if (node >= n) return;
    int lane64 = threadIdx.x & 63;
    int p0 = row_ptr[node], p1 = row_ptr[node + 1];
    float4 acc = make_float4(0.f, 0.f, 0.f, 0.f);
    for (int p = p0; p < p1; p++) {
        int s = __ldg(&csr_src[p]);
        float w = __ldg(&csr_w[p]);
        float4 v = *(const float4*)&sup[(size_t)s * FAN_MID + lane64 * 4];
        acc.x += w * v.x;
        acc.y += w * v.y;
        acc.z += w * v.z;
        acc.w += w * v.w;
    }
    float4 bb = *(const float4*)&b[lane64 * 4];
    acc.x += bb.x; acc.y += bb.y; acc.z += bb.z; acc.w += bb.w;
    acc.x = (acc.x > 0.f) ? acc.x : 0.01f * acc.x;
    acc.y = (acc.y > 0.f) ? acc.y : 0.01f * acc.y;
    acc.z = (acc.z > 0.f) ? acc.z : 0.01f * acc.z;
    acc.w = (acc.w > 0.f) ? acc.w : 0.01f * acc.w;
    *(float4*)&h[(size_t)node * FAN_MID + lane64 * 4] = acc;
}

// ---------------------------------------------------------------------------
// Gather layer 2 (F=64) fused with bias + log_softmax. 1 warp per node.
// ---------------------------------------------------------------------------
__global__ void gather2_lsm_kernel(const int* __restrict__ row_ptr, const int* __restrict__ csr_src,
                                   const float* __restrict__ csr_w,
                                   const float* __restrict__ sup, const float* __restrict__ b,
                                   float* __restrict__ out, int n) {
    int node = blockIdx.x * 8 + (threadIdx.x >> 5);
    if (node >= n) return;
    int lane = threadIdx.x & 31;
    int p0 = row_ptr[node], p1 = row_ptr[node + 1];
    float a0 = 0.f, a1 = 0.f;
    for (int p = p0; p < p1; p++) {
        int s = __ldg(&csr_src[p]);
        float w = __ldg(&csr_w[p]);
        a0 += w * sup[(size_t)s * FAN_OUT + lane];
        a1 += w * sup[(size_t)s * FAN_OUT + lane + 32];
    }
    a0 += b[lane];
    a1 += b[lane + 32];
    float m = fmaxf(a0, a1);
    #pragma unroll
    for (int o = 16; o; o >>= 1) m = fmaxf(m, __shfl_xor_sync(0xFFFFFFFFu, m, o));
    float s2 = expf(a0 - m) + expf(a1 - m);
    #pragma unroll
    for (int o = 16; o; o >>= 1) s2 += __shfl_xor_sync(0xFFFFFFFFu, s2, o);
    float lse = m + logf(s2);
    out[(size_t)node * FAN_OUT + lane]      = a0 - lse;
    out[(size_t)node * FAN_OUT + lane + 32] = a1 - lse;
}

// ---------------------------------------------------------------------------
// Launch
// ---------------------------------------------------------------------------
extern "C" void kernel_launch(void* const* d_in, const int* in_sizes, int n_in,
                              void* d_out, int out_size) {
    const float* x        = (const float*)d_in[0];
    const int*   edge_src = (const int*)  d_in[1];
    const int*   edge_dst = (const int*)  d_in[2];
    const float* edge_w1  = (const float*)d_in[3];
    const float* edge_w2  = (const float*)d_in[4];
    const float* W1       = (const float*)d_in[5];
    const float* b1       = (const float*)d_in[6];
    const float* W2       = (const float*)d_in[7];
    const float* b2       = (const float*)d_in[8];
    float* out = (float*)d_out;

    const int E = in_sizes[1];
    const int N = in_sizes[0] / FAN_IN;

    float *sup1, *h, *sup2, *csr_w1, *csr_w2;
    int *cnt, *row_ptr, *fill, *csr_src;
    cudaGetSymbolAddress((void**)&sup1, g_sup1);
    cudaGetSymbolAddress((void**)&h, g_h);
    cudaGetSymbolAddress((void**)&sup2, g_sup2);
    cudaGetSymbolAddress((void**)&cnt, g_cnt);
    cudaGetSymbolAddress((void**)&row_ptr, g_row_ptr);
    cudaGetSymbolAddress((void**)&fill, g_fill);
    cudaGetSymbolAddress((void**)&csr_src, g_csr_src);
    cudaGetSymbolAddress((void**)&csr_w1, g_csr_w1);
    cudaGetSymbolAddress((void**)&csr_w2, g_csr_w2);

    // --- CSR build ---
    zero_int_kernel<<<256, 256>>>(cnt, N);
    hist_kernel<<<2048, 256>>>(edge_dst, cnt, E);
    scan_kernel<<<1, 1024>>>(cnt, row_ptr, fill, N);
    fill_kernel<<<2048, 256>>>(edge_src, edge_dst, edge_w1, edge_w2,
                               fill, csr_src, csr_w1, csr_w2, E);

    // --- Layer 1: sup1 = x @ W1  (tf32 tensor cores) ---
    {
        dim3 grid(FAN_MID / 128, (N + 127) / 128);
        gemm_tf32_kernel<<<grid, 256>>>(x, W1, sup1, N, FAN_MID, FAN_IN);
    }
    // h = lrelu(A @ sup1 + b1)
    gather1_kernel<<<(N + 3) / 4, 256>>>(row_ptr, csr_src, csr_w1, sup1, b1, h, N);

    // --- Layer 2: sup2 = h @ W2 (fp32) ---
    {
        dim3 grid(FAN_OUT / 64, (N + 127) / 128);
        gemm_kernel<64, 4><<<grid, 256>>>(h, W2, sup2, N, FAN_OUT, FAN_MID);
    }
    // out = log_softmax(A @ sup2 + b2)
    gather2_lsm_kernel<<<(N + 7) / 8, 256>>>(row_ptr, csr_src, csr_w2, sup2, b2, out, N);
}